// round 15
// baseline (speedup 1.0000x reference)
#include <cuda_runtime.h>
#include <mma.h>
#include <math.h>

using namespace nvcuda;

// ---------------- problem constants ----------------
#define BATCH 4
#define CF    64
#define HH    128
#define WHALF 128
#define H     256
#define W     256
#define KT    51
#define OC64  64
#define NB    4
#define PADI  25
#define IMGW  306
#define HW    (H*W)
#define CFP   64        // padded cin conv1
#define KTP   56        // padded cin conv2/3

// padded smem leading dims (bank-conflict fix)
#define ALD   12        // A tile: floats per pixel (8 data + 4 pad)
#define BLD   68        // B tile: floats per k-row (64 data + 4 pad)

typedef unsigned long long u64;

__device__ __forceinline__ float to_tf32(float v) {
    return wmma::__float_to_tf32(v);
}

// ---------------- packed f32x2 helpers (sepconv) ---------------------------
__device__ __forceinline__ u64 pack2(float lo, float hi) {
    u64 r;
    asm("mov.b64 %0, {%1, %2};" : "=l"(r) : "f"(lo), "f"(hi));
    return r;
}
__device__ __forceinline__ void unpack2(u64 v, float& lo, float& hi) {
    asm("mov.b64 {%0, %1}, %2;" : "=f"(lo), "=f"(hi) : "l"(v));
}
__device__ __forceinline__ void fma2(u64& acc, u64 a, u64 b) {
    asm("fma.rn.f32x2 %0, %1, %2, %0;" : "+l"(acc) : "l"(a), "l"(b));
}

// ---------------- scratch --------------------------------------------------
__device__ float g_u  [BATCH*HW*OC64];        // NHWC, tf32-rounded
__device__ float g_h1 [BATCH*NB*HW*OC64];     // NHWC, tf32-rounded
__device__ float g_h2 [BATCH*NB*HW*OC64];     // NHWC, tf32-rounded
__device__ float g_h3 [BATCH*NB*KT*HW];       // NCHW fp32 (sepconv input)
__device__ float g_w1t[NB*9*CFP*OC64];        // [g][tap][icPad][64], tf32
__device__ float g_w2t[NB*9*KTP*OC64];
__device__ float g_w3t[NB*9*KTP*OC64];

// ---------------- 2x bilinear upsample -> NHWC + tf32 round ---------------
__global__ void upsample_k(const float* __restrict__ x)
{
    __shared__ float s[64 * 65];
    const int p0  = blockIdx.x * 64;          // linear px over BATCH*HW
    const int b   = p0 / HW;
    const int rem = p0 - b * HW;
    const int y   = rem / W;
    const int xb  = rem % W;

    const float sc = (float)(HH - 1) / (float)(H - 1);
    const float fy = (float)y * sc;
    const int   ly = (int)floorf(fy);
    const float wy = fy - (float)ly;
    const int   hy = min(ly + 1, HH - 1);

    const int tid = threadIdx.x;
    const int c   = tid >> 2;
    const int sub = tid & 3;
    const float* xc = x + ((size_t)b * CF + c) * HH * WHALF;

#pragma unroll 4
    for (int i = 0; i < 16; i++) {
        int px = sub * 16 + i;
        int gx = xb + px;
        float fx = (float)gx * sc;
        int   lx = (int)floorf(fx);
        float wx = fx - (float)lx;
        int   hx = min(lx + 1, WHALF - 1);
        float a  = xc[ly*WHALF + lx];
        float bb = xc[hy*WHALF + lx];
        float cc = xc[ly*WHALF + hx];
        float dd = xc[hy*WHALF + hx];
        float v = (a*(1.f-wy) + bb*wy)*(1.f-wx) + (cc*(1.f-wy) + dd*wy)*wx;
        s[px*65 + c] = to_tf32(v);
    }
    __syncthreads();
    float* outb = g_u + (size_t)p0 * OC64;
#pragma unroll 4
    for (int i = 0; i < 16; i++) {
        int idx = tid + 256*i;
        int cc2 = idx & 63, px = idx >> 6;
        outb[px*OC64 + cc2] = s[px*65 + cc2];
    }
}

// ------ weight transpose + tf32 round: -> [g][tap][icPad][OC64] ------------
__global__ void wprep2_k(const float* __restrict__ w, float* __restrict__ wt,
                         int cin, int cinp)
{
    int idx = blockIdx.x * blockDim.x + threadIdx.x;
    int total = NB * 9 * cinp * OC64;
    if (idx >= total) return;
    int oc  = idx & 63;
    int t   = idx >> 6;
    int ic  = t % cinp;
    t       = t / cinp;
    int tap = t % 9;
    int g   = t / 9;
    float v = 0.f;
    if (oc < KT && ic < cin)
        v = w[(((size_t)(g*KT + oc) * cin + ic) * 9) + tap];
    wt[idx] = to_tf32(v);
}

// ---------------- conv3x3 + bias + relu via wmma TF32 ----------------------
// NHWC input (stride 64/px), pre-rounded tf32 -> no per-fragment cvt.
// Block: 16x16 px, 64 oc, one (b,g). 8 warps x (2M x 4N) m16n16k8 frags.
// Smem tiles use padded leading dims (ALD=12, BLD=68) so load_matrix_sync
// rows land on distinct banks (was 8-way conflicted on B with ld=64).
// NCHW_OUT=false: NHWC tf32-rounded output (h1,h2). true: NCHW fp32 (h3).
template<int CINP, bool GROUPED, bool NCHW_OUT>
__global__ __launch_bounds__(256, 2)
void conv3x3_wmma_k(const float* __restrict__ in, const float* __restrict__ wt,
                    const float* __restrict__ bias, float* __restrict__ out)
{
    // pool: mainloop (s_in 18*18*ALD = 3888 | s_w 9*8*BLD = 4896) = 8784
    //       epilogue staging 8 warps * 16*72 = 9216  -> pool = 9216 floats
    __shared__ float s_pool[8*16*72];
    __shared__ float s_bias[64];
    float* s_in = s_pool;               // 3888 floats (15552 B, 16B-aligned)
    float* s_w  = s_pool + 3888;        // 4896 floats (end 8784)

    const int tid  = threadIdx.x;
    const int warp = tid >> 5;
    const int lane = tid & 31;
    const int x0 = blockIdx.x * 16;
    const int y0 = blockIdx.y * 16;
    const int g  = blockIdx.z % NB;
    const int b  = blockIdx.z / NB;

    const float* inb = GROUPED
        ? in + (size_t)(b*NB + g) * HW * OC64
        : in + (size_t)b * HW * OC64;
    const float* wg = wt + (size_t)g * 9 * CINP * OC64;

    if (tid < 64) s_bias[tid] = (tid < KT) ? bias[g*KT + tid] : 0.f;

    wmma::fragment<wmma::accumulator, 16, 16, 8, float> c[2][4];
#pragma unroll
    for (int mt = 0; mt < 2; mt++)
#pragma unroll
        for (int nt = 0; nt < 4; nt++)
            wmma::fill_fragment(c[mt][nt], 0.f);

    for (int ic0 = 0; ic0 < CINP; ic0 += 8) {
        __syncthreads();
        // stage input: 18x18 px, 8 ch -> 2 float4 per px (NHWC source)
        for (int li = tid; li < 324*2; li += 256) {
            int px = li >> 1, q = li & 1;
            int iy = px / 18, ix = px % 18;
            int gy = y0 + iy - 1, gx = x0 + ix - 1;
            float4 v = make_float4(0.f, 0.f, 0.f, 0.f);
            if ((unsigned)gy < H && (unsigned)gx < W)
                v = *(const float4*)(inb + ((size_t)gy*W + gx)*OC64 + ic0 + q*4);
            *(float4*)(s_in + px*ALD + q*4) = v;
        }
        // stage weights: 9 taps x 8 ic x 64 oc into BLD-padded rows
        for (int li = tid; li < 9*8*16; li += 256) {
            int oc4 = li & 15;
            int row = li >> 4;          // tap*8 + ic
            int ic  = row & 7;
            int tap = row >> 3;
            *(float4*)(s_w + row*BLD + oc4*4) =
                ((const float4*)wg)[((size_t)tap*CINP + ic0 + ic)*16 + oc4];
        }
        __syncthreads();

        const int py0 = warp * 2;
#pragma unroll
        for (int tap = 0; tap < 9; tap++) {
            const int ky = tap / 3, kx = tap % 3;
            wmma::fragment<wmma::matrix_b, 16, 16, 8,
                           wmma::precision::tf32, wmma::row_major> bf[4];
#pragma unroll
            for (int nt = 0; nt < 4; nt++)
                wmma::load_matrix_sync(bf[nt], s_w + (tap*8)*BLD + nt*16, BLD);
#pragma unroll
            for (int mt = 0; mt < 2; mt++) {
                wmma::fragment<wmma::matrix_a, 16, 16, 8,
                               wmma::precision::tf32, wmma::row_major> af;
                wmma::load_matrix_sync(af,
                    s_in + ((py0 + mt + ky)*18 + kx)*ALD, ALD);
#pragma unroll
                for (int nt = 0; nt < 4; nt++)
                    wmma::mma_sync(c[mt][nt], af, bf[nt], c[mt][nt]);
            }
        }
    }

    __syncthreads();   // s_in/s_w dead; pool becomes epilogue staging
    float* st = s_pool + warp * 16 * 72;

    if (!NCHW_OUT) {
        // NHWC tf32-rounded output (h1 / h2)
        const size_t obase = (size_t)(b*NB + g) * HW * OC64;
#pragma unroll
        for (int mt = 0; mt < 2; mt++) {
            const int py = warp*2 + mt;
#pragma unroll
            for (int nt = 0; nt < 4; nt++)
                wmma::store_matrix_sync(st + nt*16, c[mt][nt], 72,
                                        wmma::mem_row_major);
            __syncwarp();
            const int px   = lane >> 1;
            const int cofs = (lane & 1) * 32;
            const float* row = st + px*72 + cofs;
            float* orow = out + obase + ((size_t)(y0+py)*W + x0 + px)*OC64 + cofs;
#pragma unroll
            for (int j = 0; j < 8; j++) {
                int oc = cofs + j*4;
                float4 v;
                v.x = to_tf32(fmaxf(row[j*4+0] + s_bias[oc+0], 0.f));
                v.y = to_tf32(fmaxf(row[j*4+1] + s_bias[oc+1], 0.f));
                v.z = to_tf32(fmaxf(row[j*4+2] + s_bias[oc+2], 0.f));
                v.w = to_tf32(fmaxf(row[j*4+3] + s_bias[oc+3], 0.f));
                *(float4*)(orow + j*4) = v;
            }
            __syncwarp();
        }
    } else {
        // NCHW fp32 output (h3, feeds sepconv)
        const size_t obase = (size_t)(b*NB + g) * KT * HW;
#pragma unroll
        for (int mt = 0; mt < 2; mt++) {
            const int py = warp*2 + mt;
#pragma unroll
            for (int nt = 0; nt < 4; nt++) {
                wmma::store_matrix_sync(st, c[mt][nt], 72, wmma::mem_row_major);
                __syncwarp();
#pragma unroll
                for (int i = 0; i < 8; i++) {
                    int idx = lane + 32*i;
                    int m = idx & 15;
                    int n = idx >> 4;
                    int oc = nt*16 + n;
                    if (oc < KT)
                        out[obase + (size_t)oc*HW + (size_t)(y0+py)*W + x0 + m]
                            = fmaxf(st[m*72 + n] + s_bias[oc], 0.f);
                }
                __syncwarp();
            }
        }
    }
}

// ---------------- separable 51-tap conv + sum of the two frames -----------
__global__ __launch_bounds__(256, 2)
void sepconv_k(const float* __restrict__ i1, const float* __restrict__ i2,
               float* __restrict__ out)
{
    __shared__ u64 s_dup[66 * 80];
    const int tx = threadIdx.x & 15;
    const int ty = threadIdx.x >> 4;
    const int x0 = blockIdx.x * 16;
    const int y0 = blockIdx.y * 16;
    const int b  = blockIdx.z;
    const int y  = y0 + ty, x = x0 + tx;

    const float* kbase = g_h3 + (size_t)b * NB * KT * HW + (size_t)y * W + x;
    float acc[3] = {0.f, 0.f, 0.f};

    for (int im = 0; im < 2; im++) {
        const float* img = im ? i2 : i1;
        const float* kv = kbase + (size_t)(im*2    ) * KT * HW;
        const float* kh = kbase + (size_t)(im*2 + 1) * KT * HW;

        for (int c = 0; c < 3; c++) {
            __syncthreads();
            const float* ib = img + ((size_t)b * 3 + c) * IMGW * IMGW;
            for (int li = threadIdx.x; li < 66*66; li += 256) {
                int iy = li / 66, ix = li % 66;
                const float* p = ib + (size_t)(y0 + iy) * IMGW + (x0 + ix);
                float a0 = p[0];
                float a1 = (ix < 65) ? p[1] : 0.f;
                s_dup[iy*80 + ix] = pack2(a0, a1);
            }
            __syncthreads();

            u64 v2[25];
            float vlast = 0.f;
#pragma unroll
            for (int q = 0; q < 25; q++) v2[q] = 0;

            for (int i = 0; i < KT; i++) {
                float kvi = kv[(size_t)i * HW];
                u64 kv2 = pack2(kvi, kvi);
                const u64* srow = &s_dup[(ty + i) * 80 + tx];
#pragma unroll
                for (int q = 0; q < 25; q++)
                    fma2(v2[q], kv2, srow[2*q]);
                float s50 = ((const float*)&srow[50])[0];
                vlast = fmaf(kvi, s50, vlast);
            }
            float o = 0.f;
#pragma unroll
            for (int q = 0; q < 25; q++) {
                float vlo, vhi;
                unpack2(v2[q], vlo, vhi);
                o = fmaf(kh[(size_t)(2*q  ) * HW], vlo, o);
                o = fmaf(kh[(size_t)(2*q+1) * HW], vhi, o);
            }
            o = fmaf(kh[(size_t)50 * HW], vlast, o);
            acc[c] += o;
        }
    }

    size_t ob = (size_t)b * 3 * HW + (size_t)y * W + x;
#pragma unroll
    for (int c = 0; c < 3; c++)
        out[ob + (size_t)c * HW] = acc[c];
}

// ---------------- launch ---------------------------------------------------
extern "C" void kernel_launch(void* const* d_in, const int* in_sizes, int n_in,
                              void* d_out, int out_size)
{
    const float* x  = (const float*)d_in[0];
    const float* i1 = (const float*)d_in[1];
    const float* i2 = (const float*)d_in[2];
    const float* W1 = (const float*)d_in[3];
    const float* B1 = (const float*)d_in[4];
    const float* W2 = (const float*)d_in[5];
    const float* B2 = (const float*)d_in[6];
    const float* W3 = (const float*)d_in[7];
    const float* B3 = (const float*)d_in[8];
    float* out = (float*)d_out;

    float *u, *h1, *h2, *h3, *w1t, *w2t, *w3t;
    cudaGetSymbolAddress((void**)&u,   g_u);
    cudaGetSymbolAddress((void**)&h1,  g_h1);
    cudaGetSymbolAddress((void**)&h2,  g_h2);
    cudaGetSymbolAddress((void**)&h3,  g_h3);
    cudaGetSymbolAddress((void**)&w1t, g_w1t);
    cudaGetSymbolAddress((void**)&w2t, g_w2t);
    cudaGetSymbolAddress((void**)&w3t, g_w3t);

    {
        int n1 = NB*9*CFP*OC64, n2 = NB*9*KTP*OC64;
        wprep2_k<<<(n1 + 255)/256, 256>>>(W1, w1t, CF, CFP);
        wprep2_k<<<(n2 + 255)/256, 256>>>(W2, w2t, KT, KTP);
        wprep2_k<<<(n2 + 255)/256, 256>>>(W3, w3t, KT, KTP);
    }
    {
        int nblk = BATCH*HW/64;
        upsample_k<<<nblk, 256>>>(x);
    }

    dim3 cgrid(W/16, H/16, BATCH*NB);
    dim3 cblk(256);
    conv3x3_wmma_k<CFP, false, false><<<cgrid, cblk>>>(u,  w1t, B1, h1);
    conv3x3_wmma_k<KTP, true,  false><<<cgrid, cblk>>>(h1, w2t, B2, h2);
    conv3x3_wmma_k<KTP, true,  true ><<<cgrid, cblk>>>(h2, w3t, B3, h3);

    dim3 sgrid(W/16, H/16, BATCH);
    sepconv_k<<<sgrid, cblk>>>(i1, i2, out);

    (void)in_sizes; (void)n_in; (void)out_size;
}